// round 7
// baseline (speedup 1.0000x reference)
#include <cuda_runtime.h>
#include <cstdint>

// Problem constants (fixed shapes)
#define B_TOTAL   65536
#define P_DIM     41
#define L_DIM     4
#define PL        (P_DIM * L_DIM)          // 164
#define CPL       (2 * PL)                 // 328
#define BPB       32                        // batches per block
#define THREADS   256
#define NBLOCKS   (B_TOTAL / BPB)           // 2048
#define SLOSS     172                       // padded loss row stride (floats): 172%32=12 -> conflict-free
#define ST        168                       // padded packed-byte row stride (bytes)

__device__ float        g_partials[NBLOCKS];
__device__ unsigned int g_count = 0;         // ticket counter; resets to 0 each launch

__global__ __launch_bounds__(THREADS, 6)
void lace_fused_kernel(const float* __restrict__ logits,
                       const int* __restrict__ targets,
                       float* __restrict__ out)
{
    __shared__ float         sloss[BPB * SLOSS];       // 22016 B: unweighted CE loss [b][p][l]
    __shared__ unsigned char spk  [BPB * ST];          //  5376 B: (target | pred<<1) per [b][p][l]
    __shared__ float warpsums[8];
    __shared__ float redsums[8];
    __shared__ bool  isLast;

    const int tid = threadIdx.x;
    const int blk = blockIdx.x;

    // ---- Phase 1: load + compute unweighted CE, fully coalesced ----
    // One (b,p) row per thread-iteration: l0 float4, l1 float4, target int4.
    {
        const float4* gL = (const float4*)(logits  + (size_t)blk * (BPB * CPL)); // 82 f4/batch
        const int4*   gT = (const int4*)  (targets + (size_t)blk * (BPB * PL));  // 41 i4/batch

        #pragma unroll
        for (int it = 0; it < 6; ++it) {
            int i = tid + it * THREADS;                // 0..1311 = 32 batches * 41 p
            if (i < BPB * P_DIM) {
                int b = i / P_DIM;
                int p = i - b * P_DIM;

                float4 v0 = gL[b * 82 + p];            // class 0, lanes 0..3
                float4 v1 = gL[b * 82 + 41 + p];       // class 1, lanes 0..3
                int4   tg = gT[b * 41 + p];

                float L0[4] = {v0.x, v0.y, v0.z, v0.w};
                float L1[4] = {v1.x, v1.y, v1.z, v1.w};
                int   T [4] = {tg.x, tg.y, tg.z, tg.w};

                float4 ls;
                float* lsp = (float*)&ls;
                unsigned int pk = 0;
                #pragma unroll
                for (int l = 0; l < 4; ++l) {
                    // CE with C=2: loss = softplus(l_other - l_target)
                    float d = T[l] ? (L0[l] - L1[l]) : (L1[l] - L0[l]);
                    float z = fmaxf(d, 0.0f);
                    lsp[l]  = z + __logf(1.0f + __expf(d - z - z));
                    // pred = argmax (ties -> class 0)
                    unsigned int byte = (unsigned int)(T[l] & 1)
                                      | ((L1[l] > L0[l]) ? 2u : 0u);
                    pk |= byte << (l * 8);
                }

                *(float4*)&sloss[b * SLOSS + p * 4] = ls;
                *(unsigned int*)&spk[b * ST + p * 4] = pk;
            }
        }
    }

    __syncthreads();

    // ---- Phase 2: 256 threads, one (b, l) strip-half each (p split 0..20 / 21..40) ----
    float sum = 0.0f;
    {
        const int half = tid >> 7;
        const int st   = tid & 127;
        const int b = st >> 2;
        const int l = st & 3;
        const float*         pLoss = &sloss[b * SLOSS + l];
        const unsigned char* pPk   = &spk  [b * ST    + l];

        const int ph = half ? 21 : 0;
        const int np = half ? 20 : 21;

        // rolling packed-byte window (bit0=target, bit1=pred)
        int km2 = (ph > 1) ? pPk[(ph - 2) * 4] : 0;
        int km1 = (ph > 0) ? pPk[(ph - 1) * 4] : 0;
        int k0  = pPk[ph * 4];
        int kp1 = pPk[(ph + 1) * 4];
        int kp2 = pPk[(ph + 2) * 4];
        int predPrev = half ? (pPk[20 * 4] >> 1) : 0;

        #pragma unroll
        for (int i = 0; i < 21; ++i) {
            if (i >= np) break;
            const int p = ph + i;

            float loss = pLoss[p * 4];

            int t0 = k0 & 1;
            // boundary weight (binary targets -> |a-b| == a^b)
            float w = 1.0f;
            if (p > 0)          w += (float)(t0 ^ (km1 & 1));
            if (p < P_DIM - 1)  w += (float)((kp1 & 1) ^ t0);
            if (p > 1)          w += 0.5f * (float)(t0 ^ (km2 & 1));
            if (p < P_DIM - 2)  w += 0.5f * (float)((kp2 & 1) ^ t0);

            float tot = loss * w;

            int pred = k0 >> 1;
            if (p > 0 && pred != predPrev) tot += 0.001f;
            predPrev = pred;

            sum += tot;

            km2 = km1; km1 = k0; k0 = kp1; kp1 = kp2;
            kp2 = (p + 3 < P_DIM) ? pPk[(p + 3) * 4] : 0;
        }
    }

    // warp reduce (8 warps)
    #pragma unroll
    for (int o = 16; o > 0; o >>= 1)
        sum += __shfl_down_sync(0xffffffffu, sum, o);
    if ((tid & 31) == 0) warpsums[tid >> 5] = sum;
    __syncthreads();

    // ---- Per-block partial + last-block fused reduction ----
    if (tid == 0) {
        float bs = 0.0f;
        #pragma unroll
        for (int i = 0; i < 8; ++i) bs += warpsums[i];
        g_partials[blk] = bs;
        __threadfence();
        unsigned int old = atomicAdd(&g_count, 1u);
        isLast = (old == NBLOCKS - 1);
    }
    __syncthreads();

    if (isLast) {
        float s = 0.0f;
        #pragma unroll
        for (int it = 0; it < NBLOCKS / THREADS; ++it)
            s += g_partials[tid + it * THREADS];
        #pragma unroll
        for (int o = 16; o > 0; o >>= 1)
            s += __shfl_down_sync(0xffffffffu, s, o);
        if ((tid & 31) == 0) redsums[tid >> 5] = s;
        __syncthreads();
        if (tid == 0) {
            float t = 0.0f;
            #pragma unroll
            for (int i = 0; i < 8; ++i) t += redsums[i];
            out[0] = t * (1.0f / ((float)B_TOTAL * (float)P_DIM * (float)L_DIM));
            g_count = 0;                 // reset for next graph replay
        }
    }
}

extern "C" void kernel_launch(void* const* d_in, const int* in_sizes, int n_in,
                              void* d_out, int out_size)
{
    const float* logits  = (const float*)d_in[0];
    const int*   targets = (const int*)d_in[1];
    float*       out     = (float*)d_out;

    lace_fused_kernel<<<NBLOCKS, THREADS>>>(logits, targets, out);
}